// round 3
// baseline (speedup 1.0000x reference)
#include <cuda_runtime.h>
#include <cuda_bf16.h>
#include <math.h>

// ---------------------------------------------------------------------------
// RawSequenceEncoder: compress(interp) -> in-proj GEMM -> 4x conv blocks -> LN
// B=32, S=4096, D_IN=256, D=256, T=256, NB=4, K=5.  M = B*T = 8192 rows.
// ---------------------------------------------------------------------------

#define BATCH 32
#define SEQ   4096
#define DMODEL 256
#define TLEN  256
#define NBLK  4
#define KSZ   5
#define MROWS (BATCH * TLEN)   // 8192
#define EPSV  1e-5f

// ------------------------- scratch (static, no allocs) ---------------------
static __device__ float g_xc[MROWS * DMODEL];   // compressed x / conv output
static __device__ float g_h [MROWS * DMODEL];   // running hidden state
static __device__ float g_hn[MROWS * DMODEL];   // LN output / activation out
static __device__ float g_gv[MROWS * 2 * DMODEL]; // gate/value GEMM output
static __device__ int   g_len[BATCH];
static __device__ int   g_kind;                 // 0=uint8 bool, 1=int32, 2=float32

// ------------------------- reductions --------------------------------------
__device__ __forceinline__ float block_reduce_sum_256(float v, float* sh) {
    int lane = threadIdx.x & 31;
    int w    = threadIdx.x >> 5;
    #pragma unroll
    for (int o = 16; o > 0; o >>= 1) v += __shfl_down_sync(0xffffffffu, v, o);
    if (lane == 0) sh[w] = v;
    __syncthreads();
    if (w == 0) {
        v = (lane < 8) ? sh[lane] : 0.0f;
        #pragma unroll
        for (int o = 4; o > 0; o >>= 1) v += __shfl_down_sync(0xffffffffu, v, o);
        if (lane == 0) sh[0] = v;
    }
    __syncthreads();
    float r = sh[0];
    __syncthreads();   // allow sh reuse by caller
    return r;
}

// ------------------------- mask dtype detection -----------------------------
__global__ void detect_kind_kernel(const unsigned char* __restrict__ p) {
    __shared__ int s_gt1, s_nm4;
    if (threadIdx.x == 0) { s_gt1 = 0; s_nm4 = 0; }
    __syncthreads();
    int gt1 = 0, nm4 = 0;
    const int nbytes = BATCH * SEQ;   // safe lower bound for all dtypes
    for (int i = threadIdx.x; i < nbytes; i += blockDim.x) {
        unsigned char b = p[i];
        if (b > 1) gt1 = 1;
        if (b != 0 && (i & 3)) nm4 = 1;
    }
    if (gt1) atomicOr(&s_gt1, 1);
    if (nm4) atomicOr(&s_nm4, 1);
    __syncthreads();
    if (threadIdx.x == 0) g_kind = s_gt1 ? 2 : (s_nm4 ? 0 : 1);
}

__global__ void lengths_kernel(const void* __restrict__ maskv) {
    __shared__ float sh[8];
    int b = blockIdx.x;
    int kind = g_kind;
    float local = 0.0f;
    if (kind == 0) {
        const unsigned char* p = (const unsigned char*)maskv + (size_t)b * SEQ;
        for (int i = threadIdx.x; i < SEQ; i += blockDim.x) local += (float)p[i];
    } else if (kind == 1) {
        const int* p = (const int*)maskv + (size_t)b * SEQ;
        for (int i = threadIdx.x; i < SEQ; i += blockDim.x) local += (float)p[i];
    } else {
        const float* p = (const float*)maskv + (size_t)b * SEQ;
        for (int i = threadIdx.x; i < SEQ; i += blockDim.x) local += p[i];
    }
    float tot = block_reduce_sum_256(local, sh);
    if (threadIdx.x == 0) g_len[b] = (int)lrintf(tot);
}

// ------------------------- compress (linear interp gather) ------------------
__global__ void compress_kernel(const float* __restrict__ x) {
    int t = blockIdx.x;
    int b = blockIdx.y;
    int d = threadIdx.x;
    int L = g_len[b];
    float Lf  = (float)L;
    float src = ((float)t + 0.5f) * (Lf * (1.0f / (float)TLEN)) - 0.5f;
    float hi  = fmaxf(Lf - 1.0f, 0.0f);
    src = fminf(fmaxf(src, 0.0f), hi);
    int   i0 = (int)floorf(src);
    int   i1 = min(i0 + 1, max(L - 1, 0));
    float w  = src - (float)i0;
    const float* r0 = x + ((size_t)b * SEQ + i0) * DMODEL;
    const float* r1 = x + ((size_t)b * SEQ + i1) * DMODEL;
    g_xc[((size_t)(b * TLEN + t)) * DMODEL + d] = (1.0f - w) * r0[d] + w * r1[d];
}

// ------------------------- layer norm ---------------------------------------
__global__ void ln_kernel(const float* __restrict__ in,
                          const float* __restrict__ g,
                          const float* __restrict__ bta,
                          float* __restrict__ out) {
    __shared__ float sh[8];
    int m = blockIdx.x;
    int d = threadIdx.x;
    float v  = in[(size_t)m * DMODEL + d];
    float mu = block_reduce_sum_256(v, sh) * (1.0f / (float)DMODEL);
    float dv = v - mu;
    float var = block_reduce_sum_256(dv * dv, sh) * (1.0f / (float)DMODEL);
    float rs = rsqrtf(var + EPSV);
    out[(size_t)m * DMODEL + d] = dv * rs * g[d] + bta[d];
}

// ------------------------- depthwise conv K=5 along T -----------------------
__global__ void conv_kernel(const float* __restrict__ hn,
                            const float* __restrict__ w,     // [D][K]
                            const float* __restrict__ bias,  // [D]
                            float* __restrict__ out) {
    int m = blockIdx.x;        // 0..8191
    int d = threadIdx.x;
    int b = m >> 8;
    int t = m & 255;
    float acc = bias[d];
    #pragma unroll
    for (int k = 0; k < KSZ; k++) {
        int tt = t + k - (KSZ / 2);
        if (tt >= 0 && tt < TLEN)
            acc += hn[((size_t)((b << 8) + tt)) * DMODEL + d] * w[d * KSZ + k];
    }
    out[(size_t)m * DMODEL + d] = acc;
}

// ------------------------- gated activation ---------------------------------
__global__ void act_kernel(const float* __restrict__ gv, float* __restrict__ out) {
    int idx = blockIdx.x * blockDim.x + threadIdx.x;   // over MROWS*DMODEL
    int m = idx >> 8;
    int j = idx & 255;
    float gate = gv[(size_t)m * (2 * DMODEL) + j];
    float val  = gv[(size_t)m * (2 * DMODEL) + DMODEL + j];
    float sg = 1.0f / (1.0f + expf(-gate));
    float ge = 0.5f * val * (1.0f + erff(val * 0.7071067811865476f));
    out[idx] = sg * ge;
}

// ------------------------- tiled fp32 GEMM ----------------------------------
// C[M,N] = A[M,K] @ B[K,N] + bias[N] (+ resid[M,N] if non-null)
// BM=128, BN=64, BK=16, per-thread 8x4, 256 threads.
template<int BM, int BN, int BK, int TM, int TN>
__global__ __launch_bounds__(256)
void gemm_kernel(const float* __restrict__ A, const float* __restrict__ Bm,
                 const float* __restrict__ bias, const float* __restrict__ resid,
                 float* __restrict__ C, int M, int N, int K) {
    __shared__ float As[BK][BM];
    __shared__ float Bs[BK][BN];
    constexpr int NT = (BM / TM) * (BN / TN);   // 256
    const int tid = threadIdx.x;
    const int tx  = tid % (BN / TN);
    const int ty  = tid / (BN / TN);
    const int m0  = blockIdx.y * BM;
    const int n0  = blockIdx.x * BN;

    float acc[TM][TN];
    #pragma unroll
    for (int r = 0; r < TM; r++)
        #pragma unroll
        for (int c = 0; c < TN; c++) acc[r][c] = 0.0f;

    for (int k0 = 0; k0 < K; k0 += BK) {
        #pragma unroll
        for (int i = tid; i < BM * BK; i += NT) {
            int m = i / BK, k = i % BK;
            As[k][m] = A[(size_t)(m0 + m) * K + k0 + k];
        }
        #pragma unroll
        for (int i = tid; i < BK * BN; i += NT) {
            int k = i / BN, n = i % BN;
            Bs[k][n] = Bm[(size_t)(k0 + k) * N + n0 + n];
        }
        __syncthreads();
        #pragma unroll
        for (int k = 0; k < BK; k++) {
            float a[TM], bb[TN];
            #pragma unroll
            for (int r = 0; r < TM; r++) a[r] = As[k][ty * TM + r];
            #pragma unroll
            for (int c = 0; c < TN; c++) bb[c] = Bs[k][tx * TN + c];
            #pragma unroll
            for (int r = 0; r < TM; r++)
                #pragma unroll
                for (int c = 0; c < TN; c++) acc[r][c] += a[r] * bb[c];
        }
        __syncthreads();
    }

    const float4 bv = *(const float4*)(bias + n0 + tx * TN);
    #pragma unroll
    for (int r = 0; r < TM; r++) {
        int row = m0 + ty * TM + r;
        size_t base = (size_t)row * N + n0 + tx * TN;
        float4 rv = make_float4(0.f, 0.f, 0.f, 0.f);
        if (resid) rv = *(const float4*)(resid + base);
        float4 o;
        o.x = acc[r][0] + bv.x + rv.x;
        o.y = acc[r][1] + bv.y + rv.y;
        o.z = acc[r][2] + bv.z + rv.z;
        o.w = acc[r][3] + bv.w + rv.w;
        *(float4*)(C + base) = o;
    }
}

// ------------------------- mask tail ----------------------------------------
__global__ void fill_ones_kernel(float* __restrict__ p, int n) {
    int i = blockIdx.x * blockDim.x + threadIdx.x;
    if (i < n) p[i] = 1.0f;
}

// ---------------------------------------------------------------------------
extern "C" void kernel_launch(void* const* d_in, const int* in_sizes, int n_in,
                              void* d_out, int out_size) {
    const float* x      = (const float*)d_in[0];
    const void*  mask   = d_in[1];
    const float* in_w   = (const float*)d_in[2];
    const float* in_b   = (const float*)d_in[3];
    const float* ln_g   = (const float*)d_in[4];
    const float* ln_b   = (const float*)d_in[5];
    const float* dw_w   = (const float*)d_in[6];
    const float* dw_b   = (const float*)d_in[7];
    const float* win_w  = (const float*)d_in[8];
    const float* win_b  = (const float*)d_in[9];
    const float* wout_w = (const float*)d_in[10];
    const float* wout_b = (const float*)d_in[11];
    const float* fn_g   = (const float*)d_in[12];
    const float* fn_b   = (const float*)d_in[13];
    float* out = (float*)d_out;

    float *xc, *h, *hn, *gv;
    cudaGetSymbolAddress((void**)&xc, g_xc);
    cudaGetSymbolAddress((void**)&h,  g_h);
    cudaGetSymbolAddress((void**)&hn, g_hn);
    cudaGetSymbolAddress((void**)&gv, g_gv);

    // 1) mask dtype detection + lengths
    detect_kind_kernel<<<1, 256>>>((const unsigned char*)mask);
    lengths_kernel<<<BATCH, 256>>>(mask);

    // 2) compress to [B, T, D]
    compress_kernel<<<dim3(TLEN, BATCH), DMODEL>>>(x);

    // 3) input projection: h = xc @ in_w + in_b
    gemm_kernel<128, 64, 16, 8, 4><<<dim3(DMODEL / 64, MROWS / 128), 256>>>(
        xc, in_w, in_b, nullptr, h, MROWS, DMODEL, DMODEL);

    // 4) conv blocks
    for (int i = 0; i < NBLK; i++) {
        ln_kernel<<<MROWS, DMODEL>>>(h, ln_g + i * DMODEL, ln_b + i * DMODEL, hn);
        conv_kernel<<<MROWS, DMODEL>>>(hn, dw_w + i * DMODEL * KSZ,
                                       dw_b + i * DMODEL, xc);
        gemm_kernel<128, 64, 16, 8, 4><<<dim3(2 * DMODEL / 64, MROWS / 128), 256>>>(
            xc, win_w + (size_t)i * DMODEL * 2 * DMODEL, win_b + i * 2 * DMODEL,
            nullptr, gv, MROWS, 2 * DMODEL, DMODEL);
        act_kernel<<<(MROWS * DMODEL) / 256, 256>>>(gv, hn);
        gemm_kernel<128, 64, 16, 8, 4><<<dim3(DMODEL / 64, MROWS / 128), 256>>>(
            hn, wout_w + (size_t)i * DMODEL * DMODEL, wout_b + i * DMODEL,
            h /*residual*/, h, MROWS, DMODEL, DMODEL);
    }

    // 5) final layer norm -> out
    ln_kernel<<<MROWS, DMODEL>>>(h, fn_g, fn_b, out);

    // 6) comp_mask tail (all True -> 1.0f), if the harness output includes it
    int main_elems = MROWS * DMODEL;
    int extra = out_size - main_elems;
    if (extra > 0)
        fill_ones_kernel<<<(extra + 255) / 256, 256>>>(out + main_elems, extra);
}

// round 4
// speedup vs baseline: 1.3726x; 1.3726x over previous
#include <cuda_runtime.h>
#include <cuda_bf16.h>
#include <math.h>

// ---------------------------------------------------------------------------
// RawSequenceEncoder: compress(interp) -> in-proj GEMM -> 4x conv blocks -> LN
// B=32, S=4096, D_IN=256, D=256, T=256, NB=4, K=5.  M = B*T = 8192 rows.
// ---------------------------------------------------------------------------

#define BATCH 32
#define SEQ   4096
#define DMODEL 256
#define TLEN  256
#define NBLK  4
#define KSZ   5
#define MROWS (BATCH * TLEN)   // 8192
#define EPSV  1e-5f

// ------------------------- scratch (static, no allocs) ---------------------
static __device__ float g_xc[MROWS * DMODEL];   // compressed x / conv output
static __device__ float g_h [MROWS * DMODEL];   // running hidden state
static __device__ float g_hn[MROWS * DMODEL];   // activation output
static __device__ int   g_len[BATCH];
static __device__ int   g_flags[2];             // [0]=saw byte>1, [1]=nonzero at i%4!=0

// ------------------------- mask dtype detection -----------------------------
__global__ void reset_flags_kernel() {
    if (threadIdx.x < 2) g_flags[threadIdx.x] = 0;
}

__global__ void scan_mask_kernel(const unsigned char* __restrict__ p) {
    int gt1 = 0, nm4 = 0;
    const int nbytes = BATCH * SEQ;   // safe lower bound across dtypes
    for (int i = blockIdx.x * blockDim.x + threadIdx.x; i < nbytes;
         i += gridDim.x * blockDim.x) {
        unsigned char b = p[i];
        if (b > 1) gt1 = 1;
        if (b != 0 && (i & 3)) nm4 = 1;
    }
    if (gt1) atomicOr(&g_flags[0], 1);
    if (nm4) atomicOr(&g_flags[1], 1);
}

__global__ void lengths_kernel(const void* __restrict__ maskv) {
    __shared__ float sh[8];
    int b = blockIdx.x;
    int kind = g_flags[0] ? 2 : (g_flags[1] ? 0 : 1); // 2=f32, 0=u8, 1=i32
    float local = 0.0f;
    if (kind == 0) {
        const unsigned char* p = (const unsigned char*)maskv + (size_t)b * SEQ;
        for (int i = threadIdx.x; i < SEQ; i += blockDim.x) local += (float)p[i];
    } else if (kind == 1) {
        const int* p = (const int*)maskv + (size_t)b * SEQ;
        for (int i = threadIdx.x; i < SEQ; i += blockDim.x) local += (float)p[i];
    } else {
        const float* p = (const float*)maskv + (size_t)b * SEQ;
        for (int i = threadIdx.x; i < SEQ; i += blockDim.x) local += p[i];
    }
    int lane = threadIdx.x & 31, w = threadIdx.x >> 5;
    #pragma unroll
    for (int o = 16; o > 0; o >>= 1) local += __shfl_down_sync(0xffffffffu, local, o);
    if (lane == 0) sh[w] = local;
    __syncthreads();
    if (threadIdx.x == 0) {
        float tot = 0.0f;
        #pragma unroll
        for (int i = 0; i < 8; i++) tot += sh[i];
        g_len[b] = (int)lrintf(tot);
    }
}

// ------------------------- compress (linear interp gather) ------------------
__global__ void compress_kernel(const float* __restrict__ x) {
    int b = blockIdx.y;
    int t = blockIdx.x * 2 + (threadIdx.x >> 6);
    int lane = threadIdx.x & 63;
    int L = g_len[b];
    float Lf  = (float)L;
    float src = ((float)t + 0.5f) * (Lf * (1.0f / (float)TLEN)) - 0.5f;
    float hi  = fmaxf(Lf - 1.0f, 0.0f);
    src = fminf(fmaxf(src, 0.0f), hi);
    int   i0 = (int)floorf(src);
    int   i1 = min(i0 + 1, max(L - 1, 0));
    float w  = src - (float)i0;
    const float4* r0 = (const float4*)(x + ((size_t)b * SEQ + i0) * DMODEL);
    const float4* r1 = (const float4*)(x + ((size_t)b * SEQ + i1) * DMODEL);
    float4 v0 = r0[lane], v1 = r1[lane];
    float4 o;
    o.x = (1.0f - w) * v0.x + w * v1.x;
    o.y = (1.0f - w) * v0.y + w * v1.y;
    o.z = (1.0f - w) * v0.z + w * v1.z;
    o.w = (1.0f - w) * v0.w + w * v1.w;
    ((float4*)(g_xc + ((size_t)(b * TLEN + t)) * DMODEL))[lane] = o;
}

// ------------------------- fused LN + depthwise conv ------------------------
// grid (T/32, B), block 256. smem holds 36 LN-ed rows (32 + 4 halo).
__global__ __launch_bounds__(256)
void lnconv_kernel(const float* __restrict__ h,
                   const float* __restrict__ g, const float* __restrict__ bta,
                   const float* __restrict__ w, const float* __restrict__ cbias,
                   float* __restrict__ out) {
    __shared__ float sh[36][DMODEL];
    int b = blockIdx.y;
    int t0 = blockIdx.x * 32;
    int warp = threadIdx.x >> 5, lane = threadIdx.x & 31;

    for (int r = warp; r < 36; r += 8) {
        int t = t0 - 2 + r;
        if (t < 0 || t >= TLEN) {
            float4 z = make_float4(0.f, 0.f, 0.f, 0.f);
            ((float4*)sh[r])[lane * 2]     = z;
            ((float4*)sh[r])[lane * 2 + 1] = z;
        } else {
            const float4* p = (const float4*)(h + ((size_t)(b * TLEN + t)) * DMODEL);
            float4 v0 = p[lane * 2], v1 = p[lane * 2 + 1];
            float s  = v0.x + v0.y + v0.z + v0.w + v1.x + v1.y + v1.z + v1.w;
            float sq = v0.x*v0.x + v0.y*v0.y + v0.z*v0.z + v0.w*v0.w
                     + v1.x*v1.x + v1.y*v1.y + v1.z*v1.z + v1.w*v1.w;
            #pragma unroll
            for (int o = 16; o > 0; o >>= 1) {
                s  += __shfl_xor_sync(0xffffffffu, s,  o);
                sq += __shfl_xor_sync(0xffffffffu, sq, o);
            }
            float mu  = s  * (1.0f / (float)DMODEL);
            float var = sq * (1.0f / (float)DMODEL) - mu * mu;
            float rs  = rsqrtf(var + EPSV);
            const float4* gp = (const float4*)g;
            const float4* bp = (const float4*)bta;
            float4 g0 = gp[lane * 2], g1 = gp[lane * 2 + 1];
            float4 b0 = bp[lane * 2], b1 = bp[lane * 2 + 1];
            float4 o0, o1;
            o0.x = (v0.x - mu) * rs * g0.x + b0.x;
            o0.y = (v0.y - mu) * rs * g0.y + b0.y;
            o0.z = (v0.z - mu) * rs * g0.z + b0.z;
            o0.w = (v0.w - mu) * rs * g0.w + b0.w;
            o1.x = (v1.x - mu) * rs * g1.x + b1.x;
            o1.y = (v1.y - mu) * rs * g1.y + b1.y;
            o1.z = (v1.z - mu) * rs * g1.z + b1.z;
            o1.w = (v1.w - mu) * rs * g1.w + b1.w;
            ((float4*)sh[r])[lane * 2]     = o0;
            ((float4*)sh[r])[lane * 2 + 1] = o1;
        }
    }
    __syncthreads();

    int d = threadIdx.x;
    float w0 = w[d * KSZ + 0], w1 = w[d * KSZ + 1], w2 = w[d * KSZ + 2];
    float w3 = w[d * KSZ + 3], w4 = w[d * KSZ + 4];
    float cb = cbias[d];
    #pragma unroll 4
    for (int t = 0; t < 32; t++) {
        float acc = cb;
        acc = fmaf(w0, sh[t    ][d], acc);
        acc = fmaf(w1, sh[t + 1][d], acc);
        acc = fmaf(w2, sh[t + 2][d], acc);
        acc = fmaf(w3, sh[t + 3][d], acc);
        acc = fmaf(w4, sh[t + 4][d], acc);
        out[((size_t)(b * TLEN + t0 + t)) * DMODEL + d] = acc;
    }
}

// ------------------------- warp-per-row layer norm --------------------------
__global__ void ln_warp_kernel(const float* __restrict__ in,
                               const float* __restrict__ g,
                               const float* __restrict__ bta,
                               float* __restrict__ out) {
    int warp = threadIdx.x >> 5, lane = threadIdx.x & 31;
    int m = blockIdx.x * 8 + warp;
    const float4* p = (const float4*)(in + (size_t)m * DMODEL);
    float4 v0 = p[lane * 2], v1 = p[lane * 2 + 1];
    float s  = v0.x + v0.y + v0.z + v0.w + v1.x + v1.y + v1.z + v1.w;
    float sq = v0.x*v0.x + v0.y*v0.y + v0.z*v0.z + v0.w*v0.w
             + v1.x*v1.x + v1.y*v1.y + v1.z*v1.z + v1.w*v1.w;
    #pragma unroll
    for (int o = 16; o > 0; o >>= 1) {
        s  += __shfl_xor_sync(0xffffffffu, s,  o);
        sq += __shfl_xor_sync(0xffffffffu, sq, o);
    }
    float mu  = s  * (1.0f / (float)DMODEL);
    float var = sq * (1.0f / (float)DMODEL) - mu * mu;
    float rs  = rsqrtf(var + EPSV);
    const float4* gp = (const float4*)g;
    const float4* bp = (const float4*)bta;
    float4 g0 = gp[lane * 2], g1 = gp[lane * 2 + 1];
    float4 b0 = bp[lane * 2], b1 = bp[lane * 2 + 1];
    float4 o0, o1;
    o0.x = (v0.x - mu) * rs * g0.x + b0.x;
    o0.y = (v0.y - mu) * rs * g0.y + b0.y;
    o0.z = (v0.z - mu) * rs * g0.z + b0.z;
    o0.w = (v0.w - mu) * rs * g0.w + b0.w;
    o1.x = (v1.x - mu) * rs * g1.x + b1.x;
    o1.y = (v1.y - mu) * rs * g1.y + b1.y;
    o1.z = (v1.z - mu) * rs * g1.z + b1.z;
    o1.w = (v1.w - mu) * rs * g1.w + b1.w;
    ((float4*)(out + (size_t)m * DMODEL))[lane * 2]     = o0;
    ((float4*)(out + (size_t)m * DMODEL))[lane * 2 + 1] = o1;
}

// ------------------------- GEMM: 128x64 tile, 8x8 micro-tile ----------------
// C[M,256] = A[M,256] @ B[256,256] + bias (+ resid). 128 threads/block.
// Register-staged prefetch + double-buffered smem, one barrier per k-tile.
template<int WITH_RES>
__global__ __launch_bounds__(128)
void gemm128_kernel(const float* __restrict__ A, const float* __restrict__ B,
                    const float* __restrict__ bias, const float* resid,
                    float* __restrict__ C) {
    const int N = 256, K = 256;
    __shared__ float As[2][16][128];
    __shared__ float Bs[2][16][64];
    const int tid = threadIdx.x;
    const int tx = tid & 7, ty = tid >> 3;
    const int m0 = blockIdx.y * 128, n0 = blockIdx.x * 64;

    const float4* Ag = (const float4*)(A + (size_t)(m0 + tid) * K);
    const int bk0 = tid >> 4,          bn0 = tid & 15;
    const int bk1 = (tid + 128) >> 4,  bn1 = tid & 15;   // (tid+128)&15 == tid&15

    float4 a0 = Ag[0], a1 = Ag[1], a2 = Ag[2], a3 = Ag[3];
    float4 b0 = *(const float4*)(B + (size_t)bk0 * N + n0 + bn0 * 4);
    float4 b1 = *(const float4*)(B + (size_t)bk1 * N + n0 + bn1 * 4);

    float acc[8][8];
    #pragma unroll
    for (int r = 0; r < 8; r++)
        #pragma unroll
        for (int c = 0; c < 8; c++) acc[r][c] = 0.0f;

    // store tile 0
    {
        As[0][ 0][tid]=a0.x; As[0][ 1][tid]=a0.y; As[0][ 2][tid]=a0.z; As[0][ 3][tid]=a0.w;
        As[0][ 4][tid]=a1.x; As[0][ 5][tid]=a1.y; As[0][ 6][tid]=a1.z; As[0][ 7][tid]=a1.w;
        As[0][ 8][tid]=a2.x; As[0][ 9][tid]=a2.y; As[0][10][tid]=a2.z; As[0][11][tid]=a2.w;
        As[0][12][tid]=a3.x; As[0][13][tid]=a3.y; As[0][14][tid]=a3.z; As[0][15][tid]=a3.w;
        *(float4*)&Bs[0][bk0][bn0 * 4] = b0;
        *(float4*)&Bs[0][bk1][bn1 * 4] = b1;
    }
    __syncthreads();

    for (int it = 0; it < 16; ++it) {
        const int cur = it & 1;
        if (it < 15) {
            int k0 = (it + 1) * 16;
            a0 = Ag[(k0 >> 2) + 0]; a1 = Ag[(k0 >> 2) + 1];
            a2 = Ag[(k0 >> 2) + 2]; a3 = Ag[(k0 >> 2) + 3];
            b0 = *(const float4*)(B + (size_t)(k0 + bk0) * N + n0 + bn0 * 4);
            b1 = *(const float4*)(B + (size_t)(k0 + bk1) * N + n0 + bn1 * 4);
        }
        #pragma unroll
        for (int k = 0; k < 16; ++k) {
            float4 pa0 = *(const float4*)&As[cur][k][ty * 8];
            float4 pa1 = *(const float4*)&As[cur][k][ty * 8 + 4];
            float4 pb0 = *(const float4*)&Bs[cur][k][tx * 8];
            float4 pb1 = *(const float4*)&Bs[cur][k][tx * 8 + 4];
            float ar[8] = {pa0.x, pa0.y, pa0.z, pa0.w, pa1.x, pa1.y, pa1.z, pa1.w};
            float br[8] = {pb0.x, pb0.y, pb0.z, pb0.w, pb1.x, pb1.y, pb1.z, pb1.w};
            #pragma unroll
            for (int r = 0; r < 8; r++)
                #pragma unroll
                for (int c = 0; c < 8; c++)
                    acc[r][c] = fmaf(ar[r], br[c], acc[r][c]);
        }
        if (it < 15) {
            const int nxt = 1 - cur;
            As[nxt][ 0][tid]=a0.x; As[nxt][ 1][tid]=a0.y; As[nxt][ 2][tid]=a0.z; As[nxt][ 3][tid]=a0.w;
            As[nxt][ 4][tid]=a1.x; As[nxt][ 5][tid]=a1.y; As[nxt][ 6][tid]=a1.z; As[nxt][ 7][tid]=a1.w;
            As[nxt][ 8][tid]=a2.x; As[nxt][ 9][tid]=a2.y; As[nxt][10][tid]=a2.z; As[nxt][11][tid]=a2.w;
            As[nxt][12][tid]=a3.x; As[nxt][13][tid]=a3.y; As[nxt][14][tid]=a3.z; As[nxt][15][tid]=a3.w;
            *(float4*)&Bs[nxt][bk0][bn0 * 4] = b0;
            *(float4*)&Bs[nxt][bk1][bn1 * 4] = b1;
        }
        __syncthreads();
    }

    float4 bv0 = *(const float4*)(bias + n0 + tx * 8);
    float4 bv1 = *(const float4*)(bias + n0 + tx * 8 + 4);
    #pragma unroll
    for (int r = 0; r < 8; ++r) {
        size_t base = (size_t)(m0 + ty * 8 + r) * N + n0 + tx * 8;
        float4 o0, o1;
        o0.x = acc[r][0] + bv0.x; o0.y = acc[r][1] + bv0.y;
        o0.z = acc[r][2] + bv0.z; o0.w = acc[r][3] + bv0.w;
        o1.x = acc[r][4] + bv1.x; o1.y = acc[r][5] + bv1.y;
        o1.z = acc[r][6] + bv1.z; o1.w = acc[r][7] + bv1.w;
        if (WITH_RES) {
            float4 r0 = *(const float4*)(resid + base);
            float4 r1 = *(const float4*)(resid + base + 4);
            o0.x += r0.x; o0.y += r0.y; o0.z += r0.z; o0.w += r0.w;
            o1.x += r1.x; o1.y += r1.y; o1.z += r1.z; o1.w += r1.w;
        }
        *(float4*)(C + base)     = o0;
        *(float4*)(C + base + 4) = o1;
    }
}

// ------------------------- fused gated GEMM + activation --------------------
// out[M,256] = sigmoid(A@Wg + bg) * gelu(A@Wv + bv), W = win_w[256,512].
// 128x32 out-tile, 8x4 micro-tile x2 accumulators, 128 threads.
__global__ __launch_bounds__(128)
void gemm_gated_kernel(const float* __restrict__ A, const float* __restrict__ W,
                       const float* __restrict__ wb, float* __restrict__ out) {
    const int K = 256, LDB = 512, NOUT = 256;
    __shared__ float As[2][16][128];
    __shared__ float Bg[2][16][32];
    __shared__ float Bv[2][16][32];
    const int tid = threadIdx.x;
    const int tx = tid & 7, ty = tid >> 3;
    const int m0 = blockIdx.y * 128, n0 = blockIdx.x * 32;

    const float4* Ag = (const float4*)(A + (size_t)(m0 + tid) * K);
    const int bk = tid >> 3, bn = tid & 7;           // 16 k-rows x 8 float4
    const float* Wg = W + n0;
    const float* Wv = W + NOUT + n0;

    float4 a0 = Ag[0], a1 = Ag[1], a2 = Ag[2], a3 = Ag[3];
    float4 g4 = *(const float4*)(Wg + (size_t)bk * LDB + bn * 4);
    float4 v4 = *(const float4*)(Wv + (size_t)bk * LDB + bn * 4);

    float accg[8][4], accv[8][4];
    #pragma unroll
    for (int r = 0; r < 8; r++)
        #pragma unroll
        for (int c = 0; c < 4; c++) { accg[r][c] = 0.0f; accv[r][c] = 0.0f; }

    {
        As[0][ 0][tid]=a0.x; As[0][ 1][tid]=a0.y; As[0][ 2][tid]=a0.z; As[0][ 3][tid]=a0.w;
        As[0][ 4][tid]=a1.x; As[0][ 5][tid]=a1.y; As[0][ 6][tid]=a1.z; As[0][ 7][tid]=a1.w;
        As[0][ 8][tid]=a2.x; As[0][ 9][tid]=a2.y; As[0][10][tid]=a2.z; As[0][11][tid]=a2.w;
        As[0][12][tid]=a3.x; As[0][13][tid]=a3.y; As[0][14][tid]=a3.z; As[0][15][tid]=a3.w;
        *(float4*)&Bg[0][bk][bn * 4] = g4;
        *(float4*)&Bv[0][bk][bn * 4] = v4;
    }
    __syncthreads();

    for (int it = 0; it < 16; ++it) {
        const int cur = it & 1;
        if (it < 15) {
            int k0 = (it + 1) * 16;
            a0 = Ag[(k0 >> 2) + 0]; a1 = Ag[(k0 >> 2) + 1];
            a2 = Ag[(k0 >> 2) + 2]; a3 = Ag[(k0 >> 2) + 3];
            g4 = *(const float4*)(Wg + (size_t)(k0 + bk) * LDB + bn * 4);
            v4 = *(const float4*)(Wv + (size_t)(k0 + bk) * LDB + bn * 4);
        }
        #pragma unroll
        for (int k = 0; k < 16; ++k) {
            float4 pa0 = *(const float4*)&As[cur][k][ty * 8];
            float4 pa1 = *(const float4*)&As[cur][k][ty * 8 + 4];
            float4 pg  = *(const float4*)&Bg[cur][k][tx * 4];
            float4 pv  = *(const float4*)&Bv[cur][k][tx * 4];
            float ar[8] = {pa0.x, pa0.y, pa0.z, pa0.w, pa1.x, pa1.y, pa1.z, pa1.w};
            float gr[4] = {pg.x, pg.y, pg.z, pg.w};
            float vr[4] = {pv.x, pv.y, pv.z, pv.w};
            #pragma unroll
            for (int r = 0; r < 8; r++) {
                #pragma unroll
                for (int c = 0; c < 4; c++) {
                    accg[r][c] = fmaf(ar[r], gr[c], accg[r][c]);
                    accv[r][c] = fmaf(ar[r], vr[c], accv[r][c]);
                }
            }
        }
        if (it < 15) {
            const int nxt = 1 - cur;
            As[nxt][ 0][tid]=a0.x; As[nxt][ 1][tid]=a0.y; As[nxt][ 2][tid]=a0.z; As[nxt][ 3][tid]=a0.w;
            As[nxt][ 4][tid]=a1.x; As[nxt][ 5][tid]=a1.y; As[nxt][ 6][tid]=a1.z; As[nxt][ 7][tid]=a1.w;
            As[nxt][ 8][tid]=a2.x; As[nxt][ 9][tid]=a2.y; As[nxt][10][tid]=a2.z; As[nxt][11][tid]=a2.w;
            As[nxt][12][tid]=a3.x; As[nxt][13][tid]=a3.y; As[nxt][14][tid]=a3.z; As[nxt][15][tid]=a3.w;
            *(float4*)&Bg[nxt][bk][bn * 4] = g4;
            *(float4*)&Bv[nxt][bk][bn * 4] = v4;
        }
        __syncthreads();
    }

    float4 bgb = *(const float4*)(wb + n0 + tx * 4);
    float4 bvb = *(const float4*)(wb + NOUT + n0 + tx * 4);
    const float kInvSqrt2 = 0.7071067811865476f;
    #pragma unroll
    for (int r = 0; r < 8; ++r) {
        size_t base = (size_t)(m0 + ty * 8 + r) * NOUT + n0 + tx * 4;
        float gg[4] = {accg[r][0] + bgb.x, accg[r][1] + bgb.y,
                       accg[r][2] + bgb.z, accg[r][3] + bgb.w};
        float vv[4] = {accv[r][0] + bvb.x, accv[r][1] + bvb.y,
                       accv[r][2] + bvb.z, accv[r][3] + bvb.w};
        float4 o;
        float* op = (float*)&o;
        #pragma unroll
        for (int c = 0; c < 4; c++) {
            float sg = 1.0f / (1.0f + expf(-gg[c]));
            float ge = 0.5f * vv[c] * (1.0f + erff(vv[c] * kInvSqrt2));
            op[c] = sg * ge;
        }
        *(float4*)(out + base) = o;
    }
}

// ------------------------- mask tail ----------------------------------------
__global__ void fill_ones_kernel(float* __restrict__ p, int n) {
    int i = blockIdx.x * blockDim.x + threadIdx.x;
    if (i < n) p[i] = 1.0f;
}

// ---------------------------------------------------------------------------
extern "C" void kernel_launch(void* const* d_in, const int* in_sizes, int n_in,
                              void* d_out, int out_size) {
    const float* x      = (const float*)d_in[0];
    const void*  mask   = d_in[1];
    const float* in_w   = (const float*)d_in[2];
    const float* in_b   = (const float*)d_in[3];
    const float* ln_g   = (const float*)d_in[4];
    const float* ln_b   = (const float*)d_in[5];
    const float* dw_w   = (const float*)d_in[6];
    const float* dw_b   = (const float*)d_in[7];
    const float* win_w  = (const float*)d_in[8];
    const float* win_b  = (const float*)d_in[9];
    const float* wout_w = (const float*)d_in[10];
    const float* wout_b = (const float*)d_in[11];
    const float* fn_g   = (const float*)d_in[12];
    const float* fn_b   = (const float*)d_in[13];
    float* out = (float*)d_out;

    float *xc, *h, *hn;
    cudaGetSymbolAddress((void**)&xc, g_xc);
    cudaGetSymbolAddress((void**)&h,  g_h);
    cudaGetSymbolAddress((void**)&hn, g_hn);

    // 1) mask dtype detection + lengths
    reset_flags_kernel<<<1, 32>>>();
    scan_mask_kernel<<<64, 256>>>((const unsigned char*)mask);
    lengths_kernel<<<BATCH, 256>>>(mask);

    // 2) compress to [B, T, D]
    compress_kernel<<<dim3(TLEN / 2, BATCH), 128>>>(x);

    // 3) input projection: h = xc @ in_w + in_b
    gemm128_kernel<0><<<dim3(DMODEL / 64, MROWS / 128), 128>>>(
        xc, in_w, in_b, nullptr, h);

    // 4) conv blocks
    for (int i = 0; i < NBLK; i++) {
        lnconv_kernel<<<dim3(TLEN / 32, BATCH), 256>>>(
            h, ln_g + i * DMODEL, ln_b + i * DMODEL,
            dw_w + (size_t)i * DMODEL * KSZ, dw_b + i * DMODEL, xc);
        gemm_gated_kernel<<<dim3(DMODEL / 32, MROWS / 128), 128>>>(
            xc, win_w + (size_t)i * DMODEL * 2 * DMODEL,
            win_b + (size_t)i * 2 * DMODEL, hn);
        gemm128_kernel<1><<<dim3(DMODEL / 64, MROWS / 128), 128>>>(
            hn, wout_w + (size_t)i * DMODEL * DMODEL, wout_b + i * DMODEL,
            h /*residual*/, h);
    }

    // 5) final layer norm -> out
    ln_warp_kernel<<<MROWS / 8, 256>>>(h, fn_g, fn_b, out);

    // 6) comp_mask tail (all True -> 1.0f), if the harness output includes it
    int main_elems = MROWS * DMODEL;
    int extra = out_size - main_elems;
    if (extra > 0)
        fill_ones_kernel<<<(extra + 255) / 256, 256>>>(out + main_elems, extra);
}

// round 7
// speedup vs baseline: 2.9704x; 2.1641x over previous
#include <cuda_runtime.h>
#include <cuda_bf16.h>
#include <math.h>

// ---------------------------------------------------------------------------
// RawSequenceEncoder: compress -> in-proj -> 4x conv blocks -> final LN
// B=32, S=4096, D=256, T=256, NB=4, K=5. M = 8192 rows.
// GEMMs: warp-level mma.sync bf16 (sm_80 PTX path; tcgen05 is unavailable
// because the harness compiles via compute_103 without the 'a' feature set)
// with 2-term bf16 split (hh + hl + lh), fp32 accumulate.
// Round 6: identical to round 5 — that bench died with an infra-level
// "container failed twice" error before any kernel execution evidence.
// ---------------------------------------------------------------------------

#define BATCH 32
#define SEQ   4096
#define DMODEL 256
#define TLEN  256
#define NBLK  4
#define KSZ   5
#define MROWS (BATCH * TLEN)   // 8192
#define EPSV  1e-5f
#define KDIM  256

// ------------------------- scratch (static, no allocs) ---------------------
static __device__ __nv_bfloat16 g_ahi[MROWS * KDIM];  // A pair 0 (compress / lnconv out)
static __device__ __nv_bfloat16 g_alo[MROWS * KDIM];
static __device__ __nv_bfloat16 g_chi[MROWS * KDIM];  // A pair 1 (gated act out)
static __device__ __nv_bfloat16 g_clo[MROWS * KDIM];
// prepped weights [N,K] bf16: inproj(65536) + 4x wout(65536) + 4x gated(131072)
#define WOFF_IN    0
#define WOFF_WOUT(i) (65536 + (i) * 65536)
#define WOFF_GATE(i) (65536 * 5 + (i) * 131072)
#define WTOT (65536 * 5 + 131072 * 4)
static __device__ __nv_bfloat16 g_whi[WTOT];
static __device__ __nv_bfloat16 g_wlo[WTOT];
static __device__ float g_h[MROWS * DMODEL];
static __device__ int   g_len[BATCH];
static __device__ int   g_flags[2];

// ------------------------- PTX helpers (sm_80-era only) ---------------------
__device__ __forceinline__ unsigned smem_u32(const void* p) {
    unsigned a;
    asm("{ .reg .u64 t; cvta.to.shared.u64 t, %1; cvt.u32.u64 %0, t; }"
        : "=r"(a) : "l"(p));
    return a;
}
#define CP_ASYNC16(dst, src) \
    asm volatile("cp.async.cg.shared.global [%0], [%1], 16;" :: "r"(dst), "l"(src))
#define CP_COMMIT() asm volatile("cp.async.commit_group;" ::: "memory")
#define CP_WAIT(N)  asm volatile("cp.async.wait_group %0;" :: "n"(N) : "memory")

__device__ __forceinline__ void ldsm_x4(unsigned* r, unsigned addr) {
    asm volatile("ldmatrix.sync.aligned.m8n8.x4.shared.b16 {%0,%1,%2,%3}, [%4];"
                 : "=r"(r[0]), "=r"(r[1]), "=r"(r[2]), "=r"(r[3]) : "r"(addr));
}
__device__ __forceinline__ void ldsm_x2(unsigned* r, unsigned addr) {
    asm volatile("ldmatrix.sync.aligned.m8n8.x2.shared.b16 {%0,%1}, [%2];"
                 : "=r"(r[0]), "=r"(r[1]) : "r"(addr));
}
__device__ __forceinline__ void mma16816(float* d, const unsigned* a, const unsigned* b) {
    asm volatile("mma.sync.aligned.m16n8k16.row.col.f32.bf16.bf16.f32 "
                 "{%0,%1,%2,%3}, {%4,%5,%6,%7}, {%8,%9}, {%0,%1,%2,%3};"
                 : "+f"(d[0]), "+f"(d[1]), "+f"(d[2]), "+f"(d[3])
                 : "r"(a[0]), "r"(a[1]), "r"(a[2]), "r"(a[3]),
                   "r"(b[0]), "r"(b[1]));
}

__device__ __forceinline__ void splitf(float x, __nv_bfloat16& h, __nv_bfloat16& l) {
    h = __float2bfloat16_rn(x);
    l = __float2bfloat16_rn(x - __bfloat162float(h));
}

// ------------------------- mask dtype detection -----------------------------
__global__ void reset_flags_kernel() { if (threadIdx.x < 2) g_flags[threadIdx.x] = 0; }

__global__ void scan_mask_kernel(const unsigned char* __restrict__ p) {
    int gt1 = 0, nm4 = 0;
    const int nbytes = BATCH * SEQ;
    for (int i = blockIdx.x * blockDim.x + threadIdx.x; i < nbytes;
         i += gridDim.x * blockDim.x) {
        unsigned char b = p[i];
        if (b > 1) gt1 = 1;
        if (b != 0 && (i & 3)) nm4 = 1;
    }
    if (gt1) atomicOr(&g_flags[0], 1);
    if (nm4) atomicOr(&g_flags[1], 1);
}

__global__ void lengths_kernel(const void* __restrict__ maskv) {
    __shared__ float sh[8];
    int b = blockIdx.x;
    int kind = g_flags[0] ? 2 : (g_flags[1] ? 0 : 1); // 2=f32, 0=u8, 1=i32
    float local = 0.0f;
    if (kind == 0) {
        const unsigned char* p = (const unsigned char*)maskv + (size_t)b * SEQ;
        for (int i = threadIdx.x; i < SEQ; i += blockDim.x) local += (float)p[i];
    } else if (kind == 1) {
        const int* p = (const int*)maskv + (size_t)b * SEQ;
        for (int i = threadIdx.x; i < SEQ; i += blockDim.x) local += (float)p[i];
    } else {
        const float* p = (const float*)maskv + (size_t)b * SEQ;
        for (int i = threadIdx.x; i < SEQ; i += blockDim.x) local += p[i];
    }
    int lane = threadIdx.x & 31, w = threadIdx.x >> 5;
    #pragma unroll
    for (int o = 16; o > 0; o >>= 1) local += __shfl_down_sync(0xffffffffu, local, o);
    if (lane == 0) sh[w] = local;
    __syncthreads();
    if (threadIdx.x == 0) {
        float tot = 0.0f;
        #pragma unroll
        for (int i = 0; i < 8; i++) tot += sh[i];
        g_len[b] = (int)lrintf(tot);
    }
}

// ------------------------- compress -> bf16 hi/lo ----------------------------
__global__ void compress_kernel(const float* __restrict__ x) {
    int b = blockIdx.y;
    int t = blockIdx.x * 2 + (threadIdx.x >> 6);
    int lane = threadIdx.x & 63;
    int L = g_len[b];
    float Lf  = (float)L;
    float src = ((float)t + 0.5f) * (Lf * (1.0f / (float)TLEN)) - 0.5f;
    float hi  = fmaxf(Lf - 1.0f, 0.0f);
    src = fminf(fmaxf(src, 0.0f), hi);
    int   i0 = (int)floorf(src);
    int   i1 = min(i0 + 1, max(L - 1, 0));
    float w  = src - (float)i0;
    const float4* r0 = (const float4*)(x + ((size_t)b * SEQ + i0) * DMODEL);
    const float4* r1 = (const float4*)(x + ((size_t)b * SEQ + i1) * DMODEL);
    float4 v0 = r0[lane], v1 = r1[lane];
    float o[4];
    o[0] = (1.0f - w) * v0.x + w * v1.x;
    o[1] = (1.0f - w) * v0.y + w * v1.y;
    o[2] = (1.0f - w) * v0.z + w * v1.z;
    o[3] = (1.0f - w) * v0.w + w * v1.w;
    size_t base = ((size_t)(b * TLEN + t)) * DMODEL + lane * 4;
    __nv_bfloat16 h0, l0, h1, l1;
    splitf(o[0], h0, l0); splitf(o[1], h1, l1);
    __nv_bfloat162 ph0; ph0.x = h0; ph0.y = h1;
    __nv_bfloat162 pl0; pl0.x = l0; pl0.y = l1;
    splitf(o[2], h0, l0); splitf(o[3], h1, l1);
    __nv_bfloat162 ph1; ph1.x = h0; ph1.y = h1;
    __nv_bfloat162 pl1; pl1.x = l0; pl1.y = l1;
    *(__nv_bfloat162*)(g_ahi + base)     = ph0;
    *(__nv_bfloat162*)(g_ahi + base + 2) = ph1;
    *(__nv_bfloat162*)(g_alo + base)     = pl0;
    *(__nv_bfloat162*)(g_alo + base + 2) = pl1;
}

// ------------------------- weight prep: transpose + split -------------------
// out[p][k] = split(W[k][srccol(p)]).  gated: p -> gate/value 64-col pairing.
__global__ void prep_w_kernel(const float* __restrict__ W, int srcld, int gated,
                              __nv_bfloat16* __restrict__ hi,
                              __nv_bfloat16* __restrict__ lo) {
    __shared__ float t[32][33];
    int kx = blockIdx.x * 32, py = blockIdx.y * 32;
    int tx = threadIdx.x, ty = threadIdx.y;
    int p = py + tx;
    int srccol;
    if (gated) {
        int j = p >> 7, r5 = p & 127;
        srccol = j * 64 + (r5 & 63) + ((r5 & 64) ? 256 : 0);
    } else srccol = p;
    t[ty][tx] = W[(size_t)(kx + ty) * srcld + srccol];
    __syncthreads();
    int pp = py + ty, k = kx + tx;
    __nv_bfloat16 h, l;
    splitf(t[tx][ty], h, l);
    hi[(size_t)pp * KDIM + k] = h;
    lo[(size_t)pp * KDIM + k] = l;
}

// ------------------------- fused LN + conv -> bf16 hi/lo --------------------
__global__ __launch_bounds__(256)
void lnconv_kernel(const float* __restrict__ h,
                   const float* __restrict__ g, const float* __restrict__ bta,
                   const float* __restrict__ w, const float* __restrict__ cbias,
                   __nv_bfloat16* __restrict__ ohi, __nv_bfloat16* __restrict__ olo) {
    __shared__ float sh[36][DMODEL];
    int b = blockIdx.y;
    int t0 = blockIdx.x * 32;
    int warp = threadIdx.x >> 5, lane = threadIdx.x & 31;

    for (int r = warp; r < 36; r += 8) {
        int t = t0 - 2 + r;
        if (t < 0 || t >= TLEN) {
            float4 z = make_float4(0.f, 0.f, 0.f, 0.f);
            ((float4*)sh[r])[lane * 2]     = z;
            ((float4*)sh[r])[lane * 2 + 1] = z;
        } else {
            const float4* p = (const float4*)(h + ((size_t)(b * TLEN + t)) * DMODEL);
            float4 v0 = p[lane * 2], v1 = p[lane * 2 + 1];
            float s  = v0.x + v0.y + v0.z + v0.w + v1.x + v1.y + v1.z + v1.w;
            float sq = v0.x*v0.x + v0.y*v0.y + v0.z*v0.z + v0.w*v0.w
                     + v1.x*v1.x + v1.y*v1.y + v1.z*v1.z + v1.w*v1.w;
            #pragma unroll
            for (int o = 16; o > 0; o >>= 1) {
                s  += __shfl_xor_sync(0xffffffffu, s,  o);
                sq += __shfl_xor_sync(0xffffffffu, sq, o);
            }
            float mu  = s  * (1.0f / (float)DMODEL);
            float var = sq * (1.0f / (float)DMODEL) - mu * mu;
            float rs  = rsqrtf(var + EPSV);
            const float4* gp = (const float4*)g;
            const float4* bp = (const float4*)bta;
            float4 g0 = gp[lane * 2], g1 = gp[lane * 2 + 1];
            float4 b0 = bp[lane * 2], b1 = bp[lane * 2 + 1];
            float4 o0, o1;
            o0.x = (v0.x - mu) * rs * g0.x + b0.x;
            o0.y = (v0.y - mu) * rs * g0.y + b0.y;
            o0.z = (v0.z - mu) * rs * g0.z + b0.z;
            o0.w = (v0.w - mu) * rs * g0.w + b0.w;
            o1.x = (v1.x - mu) * rs * g1.x + b1.x;
            o1.y = (v1.y - mu) * rs * g1.y + b1.y;
            o1.z = (v1.z - mu) * rs * g1.z + b1.z;
            o1.w = (v1.w - mu) * rs * g1.w + b1.w;
            ((float4*)sh[r])[lane * 2]     = o0;
            ((float4*)sh[r])[lane * 2 + 1] = o1;
        }
    }
    __syncthreads();

    int d = threadIdx.x;
    float w0 = w[d * KSZ + 0], w1 = w[d * KSZ + 1], w2 = w[d * KSZ + 2];
    float w3 = w[d * KSZ + 3], w4 = w[d * KSZ + 4];
    float cb = cbias[d];
    float acc[32];
    #pragma unroll
    for (int t = 0; t < 32; t++) {
        float a = cb;
        a = fmaf(w0, sh[t    ][d], a);
        a = fmaf(w1, sh[t + 1][d], a);
        a = fmaf(w2, sh[t + 2][d], a);
        a = fmaf(w3, sh[t + 3][d], a);
        a = fmaf(w4, sh[t + 4][d], a);
        acc[t] = a;
    }
    __syncthreads();
    #pragma unroll
    for (int t = 0; t < 32; t++) sh[t][d] = acc[t];
    __syncthreads();

    size_t rowbase = (size_t)(b * TLEN + t0);
    for (int p = threadIdx.x; p < 32 * 128; p += 256) {
        int r = p >> 7, dp = (p & 127) * 2;
        __nv_bfloat16 h0, l0, h1, l1;
        splitf(sh[r][dp],     h0, l0);
        splitf(sh[r][dp + 1], h1, l1);
        __nv_bfloat162 ph; ph.x = h0; ph.y = h1;
        __nv_bfloat162 pl; pl.x = l0; pl.y = l1;
        *(__nv_bfloat162*)(ohi + (rowbase + r) * DMODEL + dp) = ph;
        *(__nv_bfloat162*)(olo + (rowbase + r) * DMODEL + dp) = pl;
    }
}

// ------------------------- warp-per-row final layer norm --------------------
__global__ void ln_warp_kernel(const float* __restrict__ in,
                               const float* __restrict__ g,
                               const float* __restrict__ bta,
                               float* __restrict__ out) {
    int warp = threadIdx.x >> 5, lane = threadIdx.x & 31;
    int m = blockIdx.x * 8 + warp;
    const float4* p = (const float4*)(in + (size_t)m * DMODEL);
    float4 v0 = p[lane * 2], v1 = p[lane * 2 + 1];
    float s  = v0.x + v0.y + v0.z + v0.w + v1.x + v1.y + v1.z + v1.w;
    float sq = v0.x*v0.x + v0.y*v0.y + v0.z*v0.z + v0.w*v0.w
             + v1.x*v1.x + v1.y*v1.y + v1.z*v1.z + v1.w*v1.w;
    #pragma unroll
    for (int o = 16; o > 0; o >>= 1) {
        s  += __shfl_xor_sync(0xffffffffu, s,  o);
        sq += __shfl_xor_sync(0xffffffffu, sq, o);
    }
    float mu  = s  * (1.0f / (float)DMODEL);
    float var = sq * (1.0f / (float)DMODEL) - mu * mu;
    float rs  = rsqrtf(var + EPSV);
    const float4* gp = (const float4*)g;
    const float4* bp = (const float4*)bta;
    float4 g0 = gp[lane * 2], g1 = gp[lane * 2 + 1];
    float4 b0 = bp[lane * 2], b1 = bp[lane * 2 + 1];
    float4 o0, o1;
    o0.x = (v0.x - mu) * rs * g0.x + b0.x;
    o0.y = (v0.y - mu) * rs * g0.y + b0.y;
    o0.z = (v0.z - mu) * rs * g0.z + b0.z;
    o0.w = (v0.w - mu) * rs * g0.w + b0.w;
    o1.x = (v1.x - mu) * rs * g1.x + b1.x;
    o1.y = (v1.y - mu) * rs * g1.y + b1.y;
    o1.z = (v1.z - mu) * rs * g1.z + b1.z;
    o1.w = (v1.w - mu) * rs * g1.w + b1.w;
    ((float4*)(out + (size_t)m * DMODEL))[lane * 2]     = o0;
    ((float4*)(out + (size_t)m * DMODEL))[lane * 2 + 1] = o1;
}

// ------------------------- mma.sync GEMM ------------------------------------
// Per CTA: D[128,128] = A[128,256] @ Bprep[128rows,256]^T, split-bf16.
// MODE 0: outf = D + bias;  MODE 1: += resid;  MODE 2: gated sigmoid*gelu
// -> bf16 hi/lo (gate = D cols 0-63, value = D cols 64-127).
// smem: 2 stages x {Ah,Al,Bh,Bl}[128][64bf16 + 8 pad] (144 B rows).
#define TSTRIDE 144
#define TILE_B  (128 * TSTRIDE)      // 18432
#define STAGE_B (4 * TILE_B)         // 73728
#define GEMM_SMEM (2 * STAGE_B)      // 147456

template<int MODE>
__global__ __launch_bounds__(256)
void gemm_mma_kernel(const __nv_bfloat16* __restrict__ Ahi,
                     const __nv_bfloat16* __restrict__ Alo,
                     const __nv_bfloat16* __restrict__ Bhi,
                     const __nv_bfloat16* __restrict__ Blo,
                     const float* __restrict__ bias, const float* __restrict__ resid,
                     float* __restrict__ outf,
                     __nv_bfloat16* __restrict__ outhi,
                     __nv_bfloat16* __restrict__ outlo) {
    extern __shared__ char sm[];
    unsigned sbase = smem_u32(sm);
    const int tid = threadIdx.x, wid = tid >> 5, lane = tid & 31;
    const int m0 = blockIdx.y * 128;
    const int nb = blockIdx.x;
    const int n0p = nb * 128;

    const char* Ah8 = (const char*)Ahi + (size_t)m0 * 512;
    const char* Al8 = (const char*)Alo + (size_t)m0 * 512;
    const char* Bh8 = (const char*)Bhi + (size_t)n0p * 512;
    const char* Bl8 = (const char*)Blo + (size_t)n0p * 512;

    auto load_stage = [&](int s, int k0) {
        unsigned dst0 = sbase + s * STAGE_B;
        int kbyte = k0 * 2;
        #pragma unroll
        for (int j = 0; j < 4; j++) {
            int i = tid + j * 256;
            int row = i >> 3, c16 = (i & 7) * 16;
            unsigned so = (unsigned)(row * TSTRIDE + c16);
            size_t go = (size_t)row * 512 + kbyte + c16;
            CP_ASYNC16(dst0 + so,              Ah8 + go);
            CP_ASYNC16(dst0 + TILE_B + so,     Al8 + go);
            CP_ASYNC16(dst0 + 2 * TILE_B + so, Bh8 + go);
            CP_ASYNC16(dst0 + 3 * TILE_B + so, Bl8 + go);
        }
        CP_COMMIT();
    };

    load_stage(0, 0);
    load_stage(1, 64);

    const int warpM = wid >> 1, warpN = wid & 1;
    float acc[2][8][4];
    #pragma unroll
    for (int mt = 0; mt < 2; mt++)
        #pragma unroll
        for (int nt = 0; nt < 8; nt++)
            #pragma unroll
            for (int e = 0; e < 4; e++) acc[mt][nt][e] = 0.0f;

    // ldmatrix per-lane address components
    const unsigned a_row = warpM * 32 + (lane & 15);
    const unsigned a_cofs = ((lane >> 4) << 3) * 2;          // bytes
    const unsigned b_row = warpN * 64 + (lane & 7);
    const unsigned b_cofs = (((lane >> 3) & 1) << 3) * 2;    // bytes

    #pragma unroll 1
    for (int i = 0; i < 4; i++) {
        if (i < 3) { CP_WAIT(1); } else { CP_WAIT(0); }
        __syncthreads();
        unsigned st  = sbase + (i & 1) * STAGE_B;
        unsigned ahb = st;
        unsigned alb = st + TILE_B;
        unsigned bhb = st + 2 * TILE_B;
        unsigned blb = st + 3 * TILE_B;
        #pragma unroll
        for (int ks = 0; ks < 4; ks++) {
            unsigned akofs = ks * 32;     // 16 bf16 = 32 bytes
            unsigned aoff = a_row * TSTRIDE + akofs + a_cofs;
            unsigned ah[2][4], al[2][4];
            ldsm_x4(ah[0], ahb + aoff);
            ldsm_x4(ah[1], ahb + aoff + 16 * TSTRIDE);
            ldsm_x4(al[0], alb + aoff);
            ldsm_x4(al[1], alb + aoff + 16 * TSTRIDE);
            unsigned boff = b_row * TSTRIDE + ks * 32 + b_cofs;
            #pragma unroll
            for (int nt = 0; nt < 8; nt++) {
                unsigned bh[2], bl[2];
                ldsm_x2(bh, bhb + boff + nt * 8 * TSTRIDE);
                ldsm_x2(bl, blb + boff + nt * 8 * TSTRIDE);
                #pragma unroll
                for (int mt = 0; mt < 2; mt++) {
                    mma16816(acc[mt][nt], ah[mt], bh);
                    mma16816(acc[mt][nt], ah[mt], bl);
                    mma16816(acc[mt][nt], al[mt], bh);
                }
            }
        }
        __syncthreads();
        if (i + 2 < 4) load_stage(i & 1, (i + 2) * 64);
    }

    // ---- epilogue: stage D through smem (132-float row stride) ----
    float* smf = (float*)sm;
    #pragma unroll
    for (int mt = 0; mt < 2; mt++) {
        #pragma unroll
        for (int nt = 0; nt < 8; nt++) {
            int r = warpM * 32 + mt * 16 + (lane >> 2);
            int c = warpN * 64 + nt * 8 + (lane & 3) * 2;
            smf[r * 132 + c]           = acc[mt][nt][0];
            smf[r * 132 + c + 1]       = acc[mt][nt][1];
            smf[(r + 8) * 132 + c]     = acc[mt][nt][2];
            smf[(r + 8) * 132 + c + 1] = acc[mt][nt][3];
        }
    }
    __syncthreads();

    if (MODE == 2) {
        const int outn0 = nb * 64;
        for (int i = tid; i < 128 * 32; i += 256) {
            int row = i >> 5, c2 = (i & 31) * 2;
            float gg0 = smf[row * 132 + c2]     + bias[outn0 + c2];
            float gg1 = smf[row * 132 + c2 + 1] + bias[outn0 + c2 + 1];
            float vv0 = smf[row * 132 + 64 + c2]     + bias[256 + outn0 + c2];
            float vv1 = smf[row * 132 + 64 + c2 + 1] + bias[256 + outn0 + c2 + 1];
            float s0 = 1.0f / (1.0f + expf(-gg0));
            float s1 = 1.0f / (1.0f + expf(-gg1));
            float e0 = 0.5f * vv0 * (1.0f + erff(vv0 * 0.7071067811865476f));
            float e1 = 0.5f * vv1 * (1.0f + erff(vv1 * 0.7071067811865476f));
            float o0 = s0 * e0, o1 = s1 * e1;
            __nv_bfloat16 h0, l0, h1, l1;
            splitf(o0, h0, l0); splitf(o1, h1, l1);
            __nv_bfloat162 ph; ph.x = h0; ph.y = h1;
            __nv_bfloat162 pl; pl.x = l0; pl.y = l1;
            size_t ob = (size_t)(m0 + row) * DMODEL + outn0 + c2;
            *(__nv_bfloat162*)(outhi + ob) = ph;
            *(__nv_bfloat162*)(outlo + ob) = pl;
        }
    } else {
        for (int i = tid; i < 128 * 32; i += 256) {
            int row = i >> 5, c4 = (i & 31) * 4;
            float4 o;
            o.x = smf[row * 132 + c4]     + bias[n0p + c4];
            o.y = smf[row * 132 + c4 + 1] + bias[n0p + c4 + 1];
            o.z = smf[row * 132 + c4 + 2] + bias[n0p + c4 + 2];
            o.w = smf[row * 132 + c4 + 3] + bias[n0p + c4 + 3];
            size_t base = (size_t)(m0 + row) * DMODEL + n0p + c4;
            if (MODE == 1) {
                float4 rr = *(const float4*)(resid + base);
                o.x += rr.x; o.y += rr.y; o.z += rr.z; o.w += rr.w;
            }
            *(float4*)(outf + base) = o;
        }
    }
}

// ------------------------- mask tail ----------------------------------------
__global__ void fill_ones_kernel(float* __restrict__ p, int n) {
    int i = blockIdx.x * blockDim.x + threadIdx.x;
    if (i < n) p[i] = 1.0f;
}

// ---------------------------------------------------------------------------
extern "C" void kernel_launch(void* const* d_in, const int* in_sizes, int n_in,
                              void* d_out, int out_size) {
    const float* x      = (const float*)d_in[0];
    const void*  mask   = d_in[1];
    const float* in_w   = (const float*)d_in[2];
    const float* in_b   = (const float*)d_in[3];
    const float* ln_g   = (const float*)d_in[4];
    const float* ln_b   = (const float*)d_in[5];
    const float* dw_w   = (const float*)d_in[6];
    const float* dw_b   = (const float*)d_in[7];
    const float* win_w  = (const float*)d_in[8];
    const float* win_b  = (const float*)d_in[9];
    const float* wout_w = (const float*)d_in[10];
    const float* wout_b = (const float*)d_in[11];
    const float* fn_g   = (const float*)d_in[12];
    const float* fn_b   = (const float*)d_in[13];
    float* out = (float*)d_out;

    __nv_bfloat16 *ahi, *alo, *chi, *clo, *whi, *wlo;
    float *h;
    cudaGetSymbolAddress((void**)&ahi, g_ahi);
    cudaGetSymbolAddress((void**)&alo, g_alo);
    cudaGetSymbolAddress((void**)&chi, g_chi);
    cudaGetSymbolAddress((void**)&clo, g_clo);
    cudaGetSymbolAddress((void**)&whi, g_whi);
    cudaGetSymbolAddress((void**)&wlo, g_wlo);
    cudaGetSymbolAddress((void**)&h,   g_h);

    cudaFuncSetAttribute(gemm_mma_kernel<0>,
        cudaFuncAttributeMaxDynamicSharedMemorySize, GEMM_SMEM);
    cudaFuncSetAttribute(gemm_mma_kernel<1>,
        cudaFuncAttributeMaxDynamicSharedMemorySize, GEMM_SMEM);
    cudaFuncSetAttribute(gemm_mma_kernel<2>,
        cudaFuncAttributeMaxDynamicSharedMemorySize, GEMM_SMEM);

    // 1) mask dtype detection + lengths
    reset_flags_kernel<<<1, 32>>>();
    scan_mask_kernel<<<64, 256>>>((const unsigned char*)mask);
    lengths_kernel<<<BATCH, 256>>>(mask);

    // 2) weight prep (transpose + bf16 split)
    dim3 pb(32, 32);
    prep_w_kernel<<<dim3(8, 8), pb>>>(in_w, 256, 0, whi + WOFF_IN, wlo + WOFF_IN);
    for (int i = 0; i < NBLK; i++) {
        prep_w_kernel<<<dim3(8, 8), pb>>>(wout_w + (size_t)i * 65536, 256, 0,
                                          whi + WOFF_WOUT(i), wlo + WOFF_WOUT(i));
        prep_w_kernel<<<dim3(8, 16), pb>>>(win_w + (size_t)i * 131072, 512, 1,
                                           whi + WOFF_GATE(i), wlo + WOFF_GATE(i));
    }

    // 3) compress to bf16 hi/lo
    compress_kernel<<<dim3(TLEN / 2, BATCH), 128>>>(x);

    // 4) input projection: h = xc @ in_w + in_b
    gemm_mma_kernel<0><<<dim3(2, 64), 256, GEMM_SMEM>>>(
        ahi, alo, whi + WOFF_IN, wlo + WOFF_IN, in_b, nullptr, h, nullptr, nullptr);

    // 5) conv blocks
    for (int i = 0; i < NBLK; i++) {
        lnconv_kernel<<<dim3(TLEN / 32, BATCH), 256>>>(
            h, ln_g + i * DMODEL, ln_b + i * DMODEL,
            dw_w + (size_t)i * DMODEL * KSZ, dw_b + i * DMODEL, ahi, alo);
        gemm_mma_kernel<2><<<dim3(4, 64), 256, GEMM_SMEM>>>(
            ahi, alo, whi + WOFF_GATE(i), wlo + WOFF_GATE(i),
            win_b + (size_t)i * 2 * DMODEL, nullptr, nullptr, chi, clo);
        gemm_mma_kernel<1><<<dim3(2, 64), 256, GEMM_SMEM>>>(
            chi, clo, whi + WOFF_WOUT(i), wlo + WOFF_WOUT(i),
            wout_b + i * DMODEL, h, h, nullptr, nullptr);
    }

    // 6) final layer norm -> out
    ln_warp_kernel<<<MROWS / 8, 256>>>(h, fn_g, fn_b, out);

    // 7) comp_mask tail (all True -> 1.0f) if present in out buffer
    int main_elems = MROWS * DMODEL;
    int extra = out_size - main_elems;
    if (extra > 0)
        fill_ones_kernel<<<(extra + 255) / 256, 256>>>(out + main_elems, extra);
}

// round 9
// speedup vs baseline: 3.0468x; 1.0257x over previous
#include <cuda_runtime.h>
#include <cuda_bf16.h>
#include <math.h>

// ---------------------------------------------------------------------------
// RawSequenceEncoder: compress -> in-proj -> 4x conv blocks -> final LN
// B=32, S=4096, D=256, T=256, NB=4, K=5. M = 8192 rows.
// GEMMs: warp-level mma.sync bf16, 2-term bf16 split (hh+hl+lh), fp32 acc.
// R9: fix R8's misaligned-address bug (smem row stride 72 -> 80 bytes; 72 is
// not 16B-aligned for ldmatrix). BK=32, 2-stage cp.async, 80KB smem -> occ 2.
// ---------------------------------------------------------------------------

#define BATCH 32
#define SEQ   4096
#define DMODEL 256
#define TLEN  256
#define NBLK  4
#define KSZ   5
#define MROWS (BATCH * TLEN)   // 8192
#define EPSV  1e-5f
#define KDIM  256

// ------------------------- scratch (static, no allocs) ---------------------
static __device__ __nv_bfloat16 g_ahi[MROWS * KDIM];
static __device__ __nv_bfloat16 g_alo[MROWS * KDIM];
static __device__ __nv_bfloat16 g_chi[MROWS * KDIM];
static __device__ __nv_bfloat16 g_clo[MROWS * KDIM];
#define WOFF_IN    0
#define WOFF_WOUT(i) (65536 + (i) * 65536)
#define WOFF_GATE(i) (65536 * 5 + (i) * 131072)
#define WTOT (65536 * 5 + 131072 * 4)
static __device__ __nv_bfloat16 g_whi[WTOT];
static __device__ __nv_bfloat16 g_wlo[WTOT];
static __device__ float g_h[MROWS * DMODEL];
static __device__ int   g_len[BATCH];

// ------------------------- PTX helpers (sm_80-era only) ---------------------
__device__ __forceinline__ unsigned smem_u32(const void* p) {
    unsigned a;
    asm("{ .reg .u64 t; cvta.to.shared.u64 t, %1; cvt.u32.u64 %0, t; }"
        : "=r"(a) : "l"(p));
    return a;
}
#define CP_ASYNC16(dst, src) \
    asm volatile("cp.async.cg.shared.global [%0], [%1], 16;" :: "r"(dst), "l"(src))
#define CP_COMMIT() asm volatile("cp.async.commit_group;" ::: "memory")
#define CP_WAIT(N)  asm volatile("cp.async.wait_group %0;" :: "n"(N) : "memory")

__device__ __forceinline__ void ldsm_x4(unsigned* r, unsigned addr) {
    asm volatile("ldmatrix.sync.aligned.m8n8.x4.shared.b16 {%0,%1,%2,%3}, [%4];"
                 : "=r"(r[0]), "=r"(r[1]), "=r"(r[2]), "=r"(r[3]) : "r"(addr));
}
__device__ __forceinline__ void ldsm_x2(unsigned* r, unsigned addr) {
    asm volatile("ldmatrix.sync.aligned.m8n8.x2.shared.b16 {%0,%1}, [%2];"
                 : "=r"(r[0]), "=r"(r[1]) : "r"(addr));
}
__device__ __forceinline__ void mma16816(float* d, const unsigned* a, const unsigned* b) {
    asm volatile("mma.sync.aligned.m16n8k16.row.col.f32.bf16.bf16.f32 "
                 "{%0,%1,%2,%3}, {%4,%5,%6,%7}, {%8,%9}, {%0,%1,%2,%3};"
                 : "+f"(d[0]), "+f"(d[1]), "+f"(d[2]), "+f"(d[3])
                 : "r"(a[0]), "r"(a[1]), "r"(a[2]), "r"(a[3]),
                   "r"(b[0]), "r"(b[1]));
}

__device__ __forceinline__ void splitf(float x, __nv_bfloat16& h, __nv_bfloat16& l) {
    h = __float2bfloat16_rn(x);
    l = __float2bfloat16_rn(x - __bfloat162float(h));
}

// ------------------------- fused mask detect + lengths ----------------------
__global__ __launch_bounds__(256)
void lengths_kernel(const unsigned char* __restrict__ maskp) {
    __shared__ float sh[8];
    __shared__ int sflags;   // bit0 = saw byte>1 (f32), bit1 = nonzero at i%4!=0 (u8)
    int b = blockIdx.x;
    if (threadIdx.x == 0) sflags = 0;
    __syncthreads();

    const unsigned* pw = (const unsigned*)maskp;
    const int nwords = (BATCH * SEQ) / 4;   // safe lower bound across dtypes
    int fl = 0;
    for (int i = threadIdx.x; i < nwords; i += 256) {
        unsigned w = pw[i];
        unsigned b0 = w & 0xFF, b1 = (w >> 8) & 0xFF,
                 b2 = (w >> 16) & 0xFF, b3 = w >> 24;
        if (b0 > 1 || b1 > 1 || b2 > 1 || b3 > 1) fl |= 1;
        if (w & 0xFFFFFF00u) fl |= 2;
    }
    if (__any_sync(0xffffffffu, fl & 1)) fl |= 1;
    if (__any_sync(0xffffffffu, fl & 2)) fl |= 2;
    if ((threadIdx.x & 31) == 0 && fl) atomicOr(&sflags, fl);
    __syncthreads();
    int kind = (sflags & 1) ? 2 : ((sflags & 2) ? 0 : 1); // 2=f32, 0=u8, 1=i32

    float local = 0.0f;
    if (kind == 0) {
        const unsigned char* p = maskp + (size_t)b * SEQ;
        for (int i = threadIdx.x; i < SEQ; i += 256) local += (float)p[i];
    } else if (kind == 1) {
        const int* p = (const int*)maskp + (size_t)b * SEQ;
        for (int i = threadIdx.x; i < SEQ; i += 256) local += (float)p[i];
    } else {
        const float* p = (const float*)maskp + (size_t)b * SEQ;
        for (int i = threadIdx.x; i < SEQ; i += 256) local += p[i];
    }
    int lane = threadIdx.x & 31, w = threadIdx.x >> 5;
    #pragma unroll
    for (int o = 16; o > 0; o >>= 1) local += __shfl_down_sync(0xffffffffu, local, o);
    if (lane == 0) sh[w] = local;
    __syncthreads();
    if (threadIdx.x == 0) {
        float tot = 0.0f;
        #pragma unroll
        for (int i = 0; i < 8; i++) tot += sh[i];
        g_len[b] = (int)lrintf(tot);
    }
}

// ------------------------- compress -> bf16 hi/lo ----------------------------
__global__ void compress_kernel(const float* __restrict__ x) {
    int b = blockIdx.y;
    int t = blockIdx.x * 2 + (threadIdx.x >> 6);
    int lane = threadIdx.x & 63;
    int L = g_len[b];
    float Lf  = (float)L;
    float src = ((float)t + 0.5f) * (Lf * (1.0f / (float)TLEN)) - 0.5f;
    float hi  = fmaxf(Lf - 1.0f, 0.0f);
    src = fminf(fmaxf(src, 0.0f), hi);
    int   i0 = (int)floorf(src);
    int   i1 = min(i0 + 1, max(L - 1, 0));
    float w  = src - (float)i0;
    const float4* r0 = (const float4*)(x + ((size_t)b * SEQ + i0) * DMODEL);
    const float4* r1 = (const float4*)(x + ((size_t)b * SEQ + i1) * DMODEL);
    float4 v0 = r0[lane], v1 = r1[lane];
    float o[4];
    o[0] = (1.0f - w) * v0.x + w * v1.x;
    o[1] = (1.0f - w) * v0.y + w * v1.y;
    o[2] = (1.0f - w) * v0.z + w * v1.z;
    o[3] = (1.0f - w) * v0.w + w * v1.w;
    size_t base = ((size_t)(b * TLEN + t)) * DMODEL + lane * 4;
    __nv_bfloat16 h0, l0, h1, l1;
    splitf(o[0], h0, l0); splitf(o[1], h1, l1);
    __nv_bfloat162 ph0; ph0.x = h0; ph0.y = h1;
    __nv_bfloat162 pl0; pl0.x = l0; pl0.y = l1;
    splitf(o[2], h0, l0); splitf(o[3], h1, l1);
    __nv_bfloat162 ph1; ph1.x = h0; ph1.y = h1;
    __nv_bfloat162 pl1; pl1.x = l0; pl1.y = l1;
    *(__nv_bfloat162*)(g_ahi + base)     = ph0;
    *(__nv_bfloat162*)(g_ahi + base + 2) = ph1;
    *(__nv_bfloat162*)(g_alo + base)     = pl0;
    *(__nv_bfloat162*)(g_alo + base + 2) = pl1;
}

// ------------------------- fused weight prep (ONE launch) -------------------
__global__ void prep_all_w_kernel(const float* __restrict__ in_w,
                                  const float* __restrict__ wout_w,
                                  const float* __restrict__ win_w,
                                  __nv_bfloat16* __restrict__ hi,
                                  __nv_bfloat16* __restrict__ lo) {
    __shared__ float t[32][33];
    int bid = blockIdx.x;
    const float* W;
    int srcld, gated, tile;
    size_t dsto;
    if (bid < 64) {
        W = in_w; srcld = 256; gated = 0; dsto = WOFF_IN; tile = bid;
    } else if (bid < 320) {
        int tt = bid - 64, i = tt >> 6;
        W = wout_w + (size_t)i * 65536; srcld = 256; gated = 0;
        dsto = WOFF_WOUT(i); tile = tt & 63;
    } else {
        int tt = bid - 320, i = tt >> 7;
        W = win_w + (size_t)i * 131072; srcld = 512; gated = 1;
        dsto = WOFF_GATE(i); tile = tt & 127;
    }
    int kx = (tile & 7) * 32, py = (tile >> 3) * 32;
    int tx = threadIdx.x, ty = threadIdx.y;
    int p = py + tx;
    int srccol;
    if (gated) {
        int j = p >> 7, r5 = p & 127;
        srccol = j * 64 + (r5 & 63) + ((r5 & 64) ? 256 : 0);
    } else srccol = p;
    t[ty][tx] = W[(size_t)(kx + ty) * srcld + srccol];
    __syncthreads();
    int pp = py + ty, k = kx + tx;
    __nv_bfloat16 h, l;
    splitf(t[tx][ty], h, l);
    hi[dsto + (size_t)pp * KDIM + k] = h;
    lo[dsto + (size_t)pp * KDIM + k] = l;
}

// ------------------------- fused LN + conv -> bf16 hi/lo --------------------
__global__ __launch_bounds__(256)
void lnconv_kernel(const float* __restrict__ h,
                   const float* __restrict__ g, const float* __restrict__ bta,
                   const float* __restrict__ w, const float* __restrict__ cbias,
                   __nv_bfloat16* __restrict__ ohi, __nv_bfloat16* __restrict__ olo) {
    __shared__ float sh[36][DMODEL];
    int b = blockIdx.y;
    int t0 = blockIdx.x * 32;
    int warp = threadIdx.x >> 5, lane = threadIdx.x & 31;

    for (int r = warp; r < 36; r += 8) {
        int t = t0 - 2 + r;
        if (t < 0 || t >= TLEN) {
            float4 z = make_float4(0.f, 0.f, 0.f, 0.f);
            ((float4*)sh[r])[lane * 2]     = z;
            ((float4*)sh[r])[lane * 2 + 1] = z;
        } else {
            const float4* p = (const float4*)(h + ((size_t)(b * TLEN + t)) * DMODEL);
            float4 v0 = p[lane * 2], v1 = p[lane * 2 + 1];
            float s  = v0.x + v0.y + v0.z + v0.w + v1.x + v1.y + v1.z + v1.w;
            float sq = v0.x*v0.x + v0.y*v0.y + v0.z*v0.z + v0.w*v0.w
                     + v1.x*v1.x + v1.y*v1.y + v1.z*v1.z + v1.w*v1.w;
            #pragma unroll
            for (int o = 16; o > 0; o >>= 1) {
                s  += __shfl_xor_sync(0xffffffffu, s,  o);
                sq += __shfl_xor_sync(0xffffffffu, sq, o);
            }
            float mu  = s  * (1.0f / (float)DMODEL);
            float var = sq * (1.0f / (float)DMODEL) - mu * mu;
            float rs  = rsqrtf(var + EPSV);
            const float4* gp = (const float4*)g;
            const float4* bp = (const float4*)bta;
            float4 g0 = gp[lane * 2], g1 = gp[lane * 2 + 1];
            float4 b0 = bp[lane * 2], b1 = bp[lane * 2 + 1];
            float4 o0, o1;
            o0.x = (v0.x - mu) * rs * g0.x + b0.x;
            o0.y = (v0.y - mu) * rs * g0.y + b0.y;
            o0.z = (v0.z - mu) * rs * g0.z + b0.z;
            o0.w = (v0.w - mu) * rs * g0.w + b0.w;
            o1.x = (v1.x - mu) * rs * g1.x + b1.x;
            o1.y = (v1.y - mu) * rs * g1.y + b1.y;
            o1.z = (v1.z - mu) * rs * g1.z + b1.z;
            o1.w = (v1.w - mu) * rs * g1.w + b1.w;
            ((float4*)sh[r])[lane * 2]     = o0;
            ((float4*)sh[r])[lane * 2 + 1] = o1;
        }
    }
    __syncthreads();

    int d = threadIdx.x;
    float w0 = w[d * KSZ + 0], w1 = w[d * KSZ + 1], w2 = w[d * KSZ + 2];
    float w3 = w[d * KSZ + 3], w4 = w[d * KSZ + 4];
    float cb = cbias[d];
    float acc[32];
    #pragma unroll
    for (int t = 0; t < 32; t++) {
        float a = cb;
        a = fmaf(w0, sh[t    ][d], a);
        a = fmaf(w1, sh[t + 1][d], a);
        a = fmaf(w2, sh[t + 2][d], a);
        a = fmaf(w3, sh[t + 3][d], a);
        a = fmaf(w4, sh[t + 4][d], a);
        acc[t] = a;
    }
    __syncthreads();
    #pragma unroll
    for (int t = 0; t < 32; t++) sh[t][d] = acc[t];
    __syncthreads();

    size_t rowbase = (size_t)(b * TLEN + t0);
    for (int p = threadIdx.x; p < 32 * 128; p += 256) {
        int r = p >> 7, dp = (p & 127) * 2;
        __nv_bfloat16 h0, l0, h1, l1;
        splitf(sh[r][dp],     h0, l0);
        splitf(sh[r][dp + 1], h1, l1);
        __nv_bfloat162 ph; ph.x = h0; ph.y = h1;
        __nv_bfloat162 pl; pl.x = l0; pl.y = l1;
        *(__nv_bfloat162*)(ohi + (rowbase + r) * DMODEL + dp) = ph;
        *(__nv_bfloat162*)(olo + (rowbase + r) * DMODEL + dp) = pl;
    }
}

// ------------------------- warp-per-row final layer norm --------------------
__global__ void ln_warp_kernel(const float* __restrict__ in,
                               const float* __restrict__ g,
                               const float* __restrict__ bta,
                               float* __restrict__ out) {
    int warp = threadIdx.x >> 5, lane = threadIdx.x & 31;
    int m = blockIdx.x * 8 + warp;
    const float4* p = (const float4*)(in + (size_t)m * DMODEL);
    float4 v0 = p[lane * 2], v1 = p[lane * 2 + 1];
    float s  = v0.x + v0.y + v0.z + v0.w + v1.x + v1.y + v1.z + v1.w;
    float sq = v0.x*v0.x + v0.y*v0.y + v0.z*v0.z + v0.w*v0.w
             + v1.x*v1.x + v1.y*v1.y + v1.z*v1.z + v1.w*v1.w;
    #pragma unroll
    for (int o = 16; o > 0; o >>= 1) {
        s  += __shfl_xor_sync(0xffffffffu, s,  o);
        sq += __shfl_xor_sync(0xffffffffu, sq, o);
    }
    float mu  = s  * (1.0f / (float)DMODEL);
    float var = sq * (1.0f / (float)DMODEL) - mu * mu;
    float rs  = rsqrtf(var + EPSV);
    const float4* gp = (const float4*)g;
    const float4* bp = (const float4*)bta;
    float4 g0 = gp[lane * 2], g1 = gp[lane * 2 + 1];
    float4 b0 = bp[lane * 2], b1 = bp[lane * 2 + 1];
    float4 o0, o1;
    o0.x = (v0.x - mu) * rs * g0.x + b0.x;
    o0.y = (v0.y - mu) * rs * g0.y + b0.y;
    o0.z = (v0.z - mu) * rs * g0.z + b0.z;
    o0.w = (v0.w - mu) * rs * g0.w + b0.w;
    o1.x = (v1.x - mu) * rs * g1.x + b1.x;
    o1.y = (v1.y - mu) * rs * g1.y + b1.y;
    o1.z = (v1.z - mu) * rs * g1.z + b1.z;
    o1.w = (v1.w - mu) * rs * g1.w + b1.w;
    ((float4*)(out + (size_t)m * DMODEL))[lane * 2]     = o0;
    ((float4*)(out + (size_t)m * DMODEL))[lane * 2 + 1] = o1;
}

// ------------------------- mma.sync GEMM (BK=32, 2-stage, occ 2) ------------
// Per CTA: D[128,128] = A[128,256] @ Bprep[128rows,256]^T, split-bf16.
// MODE 0: outf = D + bias;  MODE 1: += resid;  MODE 2: gated sigmoid*gelu
// -> bf16 hi/lo (gate = D cols 0-63, value = D cols 64-127).
// smem: 2 stages x {Ah,Al,Bh,Bl}[128 rows x 80 B] = 81920 B -> 2 CTAs/SM.
// Row stride 80 B = 5x16: ldmatrix 16B-aligned; 20-bank row shift covers all
// 32 banks across the 8 rows of an ldmatrix tile (conflict-free).
#define TS2    80
#define TILE2  (128 * TS2)      // 10240
#define STAGE2 (4 * TILE2)      // 40960
#define GEMM_SMEM (2 * STAGE2)  // 81920

template<int MODE>
__global__ __launch_bounds__(256, 2)
void gemm_mma_kernel(const __nv_bfloat16* __restrict__ Ahi,
                     const __nv_bfloat16* __restrict__ Alo,
                     const __nv_bfloat16* __restrict__ Bhi,
                     const __nv_bfloat16* __restrict__ Blo,
                     const float* __restrict__ bias, const float* __restrict__ resid,
                     float* __restrict__ outf,
                     __nv_bfloat16* __restrict__ outhi,
                     __nv_bfloat16* __restrict__ outlo) {
    extern __shared__ char sm[];
    unsigned sbase = smem_u32(sm);
    const int tid = threadIdx.x, wid = tid >> 5, lane = tid & 31;
    const int m0 = blockIdx.y * 128;
    const int nb = blockIdx.x;
    const int n0p = nb * 128;

    const char* Ah8 = (const char*)Ahi + (size_t)m0 * 512;
    const char* Al8 = (const char*)Alo + (size_t)m0 * 512;
    const char* Bh8 = (const char*)Bhi + (size_t)n0p * 512;
    const char* Bl8 = (const char*)Blo + (size_t)n0p * 512;

    auto load_stage = [&](int s, int k0) {
        unsigned dst0 = sbase + s * STAGE2;
        int kbyte = k0 * 2;
        #pragma unroll
        for (int j = 0; j < 2; j++) {
            int i = tid + j * 256;
            int row = i >> 2, c16 = (i & 3) * 16;
            unsigned so = (unsigned)(row * TS2 + c16);
            size_t go = (size_t)row * 512 + kbyte + c16;
            CP_ASYNC16(dst0 + so,              Ah8 + go);
            CP_ASYNC16(dst0 + TILE2 + so,      Al8 + go);
            CP_ASYNC16(dst0 + 2 * TILE2 + so,  Bh8 + go);
            CP_ASYNC16(dst0 + 3 * TILE2 + so,  Bl8 + go);
        }
        CP_COMMIT();
    };

    load_stage(0, 0);
    load_stage(1, 32);

    const int warpM = wid >> 1, warpN = wid & 1;
    float acc[2][8][4];
    #pragma unroll
    for (int mt = 0; mt < 2; mt++)
        #pragma unroll
        for (int nt = 0; nt < 8; nt++)
            #pragma unroll
            for (int e = 0; e < 4; e++) acc[mt][nt][e] = 0.0f;

    const unsigned a_row = warpM * 32 + (lane & 15);
    const unsigned a_cofs = ((lane >> 4) << 3) * 2;          // 0 or 16 bytes
    const unsigned b_row = warpN * 64 + (lane & 7);
    const unsigned b_cofs = (((lane >> 3) & 1) << 3) * 2;    // 0 or 16 bytes

    #pragma unroll 1
    for (int i = 0; i < 8; i++) {
        if (i < 7) { CP_WAIT(1); } else { CP_WAIT(0); }
        __syncthreads();
        int buf = i & 1;
        unsigned st  = sbase + buf * STAGE2;
        unsigned ahb = st;
        unsigned alb = st + TILE2;
        unsigned bhb = st + 2 * TILE2;
        unsigned blb = st + 3 * TILE2;
        #pragma unroll
        for (int ks = 0; ks < 2; ks++) {
            unsigned aoff = a_row * TS2 + ks * 32 + a_cofs;
            unsigned ah[2][4], al[2][4];
            ldsm_x4(ah[0], ahb + aoff);
            ldsm_x4(ah[1], ahb + aoff + 16 * TS2);
            ldsm_x4(al[0], alb + aoff);
            ldsm_x4(al[1], alb + aoff + 16 * TS2);
            unsigned boff = b_row * TS2 + ks * 32 + b_cofs;
            #pragma unroll
            for (int nt = 0; nt < 8; nt++) {
                unsigned bh[2], bl[2];
                ldsm_x2(bh, bhb + boff + nt * 8 * TS2);
                ldsm_x2(bl, blb + boff + nt * 8 * TS2);
                #pragma unroll
                for (int mt = 0; mt < 2; mt++) {
                    mma16816(acc[mt][nt], ah[mt], bh);
                    mma16816(acc[mt][nt], ah[mt], bl);
                    mma16816(acc[mt][nt], al[mt], bh);
                }
            }
        }
        __syncthreads();
        if (i + 2 < 8) load_stage(buf, (i + 2) * 32);
    }

    // ---- epilogue: stage D through smem (132-float row stride, 67.6KB) ----
    float* smf = (float*)sm;
    #pragma unroll
    for (int mt = 0; mt < 2; mt++) {
        #pragma unroll
        for (int nt = 0; nt < 8; nt++) {
            int r = warpM * 32 + mt * 16 + (lane >> 2);
            int c = warpN * 64 + nt * 8 + (lane & 3) * 2;
            smf[r * 132 + c]           = acc[mt][nt][0];
            smf[r * 132 + c + 1]       = acc[mt][nt][1];
            smf[(r + 8) * 132 + c]     = acc[mt][nt][2];
            smf[(r + 8) * 132 + c + 1] = acc[mt][nt][3];
        }
    }
    __syncthreads();

    if (MODE == 2) {
        const int outn0 = nb * 64;
        for (int i = tid; i < 128 * 32; i += 256) {
            int row = i >> 5, c2 = (i & 31) * 2;
            float gg0 = smf[row * 132 + c2]     + bias[outn0 + c2];
            float gg1 = smf[row * 132 + c2 + 1] + bias[outn0 + c2 + 1];
            float vv0 = smf[row * 132 + 64 + c2]     + bias[256 + outn0 + c2];
            float vv1 = smf[row * 132 + 64 + c2 + 1] + bias[256 + outn0 + c2 + 1];
            float s0 = 1.0f / (1.0f + expf(-gg0));
            float s1 = 1.0f / (1.0f + expf(-gg1));
            float e0 = 0.5f * vv0 * (1.0f + erff(vv0 * 0.7071067811865476f));
            float e1 = 0.5f * vv1 * (1.0f + erff(vv1 * 0.7071067811865476f));
            float o0 = s0 * e0, o1 = s1 * e1;
            __nv_bfloat16 h0, l0, h1, l1;
            splitf(o0, h0, l0); splitf(o1, h1, l1);
            __nv_bfloat162 ph; ph.x = h0; ph.y = h1;
            __nv_bfloat162 pl; pl.x = l0; pl.y = l1;
            size_t ob = (size_t)(m0 + row) * DMODEL + outn0 + c2;
            *(__nv_bfloat162*)(outhi + ob) = ph;
            *(__nv_bfloat162*)(outlo + ob) = pl;
        }
    } else {
        for (int i = tid; i < 128 * 32; i += 256) {
            int row = i >> 5, c4 = (i & 31) * 4;
            float4 o;
            o.x = smf[row * 132 + c4]     + bias[n0p + c4];
            o.y = smf[row * 132 + c4 + 1] + bias[n0p + c4 + 1];
            o.z = smf[row * 132 + c4 + 2] + bias[n0p + c4 + 2];
            o.w = smf[row * 132 + c4 + 3] + bias[n0p + c4 + 3];
            size_t base = (size_t)(m0 + row) * DMODEL + n0p + c4;
            if (MODE == 1) {
                float4 rr = *(const float4*)(resid + base);
                o.x += rr.x; o.y += rr.y; o.z += rr.z; o.w += rr.w;
            }
            *(float4*)(outf + base) = o;
        }
    }
}

// ------------------------- mask tail ----------------------------------------
__global__ void fill_ones_kernel(float* __restrict__ p, int n) {
    int i = blockIdx.x * blockDim.x + threadIdx.x;
    if (i < n) p[i] = 1.0f;
}

// ---------------------------------------------------------------------------
extern "C" void kernel_launch(void* const* d_in, const int* in_sizes, int n_in,
                              void* d_out, int out_size) {
    const float* x      = (const float*)d_in[0];
    const void*  mask   = d_in[1];
    const float* in_w   = (const float*)d_in[2];
    const float* in_b   = (const float*)d_in[3];
    const float* ln_g   = (const float*)d_in[4];
    const float* ln_b   = (const float*)d_in[5];
    const float* dw_w   = (const float*)d_in[6];
    const float* dw_b   = (const float*)d_in[7];
    const float* win_w  = (const float*)d_in[8];
    const float* win_b  = (const float*)d_in[9];
    const float* wout_w = (const float*)d_in[10];
    const float* wout_b = (const float*)d_in[11];
    const float* fn_g   = (const float*)d_in[12];
    const float* fn_b   = (const float*)d_in[13];
    float* out = (float*)d_out;

    __nv_bfloat16 *ahi, *alo, *chi, *clo, *whi, *wlo;
    float *h;
    cudaGetSymbolAddress((void**)&ahi, g_ahi);
    cudaGetSymbolAddress((void**)&alo, g_alo);
    cudaGetSymbolAddress((void**)&chi, g_chi);
    cudaGetSymbolAddress((void**)&clo, g_clo);
    cudaGetSymbolAddress((void**)&whi, g_whi);
    cudaGetSymbolAddress((void**)&wlo, g_wlo);
    cudaGetSymbolAddress((void**)&h,   g_h);

    cudaFuncSetAttribute(gemm_mma_kernel<0>,
        cudaFuncAttributeMaxDynamicSharedMemorySize, GEMM_SMEM);
    cudaFuncSetAttribute(gemm_mma_kernel<1>,
        cudaFuncAttributeMaxDynamicSharedMemorySize, GEMM_SMEM);
    cudaFuncSetAttribute(gemm_mma_kernel<2>,
        cudaFuncAttributeMaxDynamicSharedMemorySize, GEMM_SMEM);

    // 1) mask dtype detection + lengths (one launch)
    lengths_kernel<<<BATCH, 256>>>((const unsigned char*)mask);

    // 2) fused weight prep (one launch: 64 + 4*64 + 4*128 = 832 blocks)
    prep_all_w_kernel<<<832, dim3(32, 32)>>>(in_w, wout_w, win_w, whi, wlo);

    // 3) compress to bf16 hi/lo
    compress_kernel<<<dim3(TLEN / 2, BATCH), 128>>>(x);

    // 4) input projection: h = xc @ in_w + in_b
    gemm_mma_kernel<0><<<dim3(2, 64), 256, GEMM_SMEM>>>(
        ahi, alo, whi + WOFF_IN, wlo + WOFF_IN, in_b, nullptr, h, nullptr, nullptr);

    // 5) conv blocks
    for (int i = 0; i < NBLK; i++) {
        lnconv_kernel<<<dim3(TLEN / 32, BATCH), 256>>>(
            h, ln_g + i * DMODEL, ln_b + i * DMODEL,
            dw_w + (size_t)i * DMODEL * KSZ, dw_b + i * DMODEL, ahi, alo);
        gemm_mma_kernel<2><<<dim3(4, 64), 256, GEMM_SMEM>>>(
            ahi, alo, whi + WOFF_GATE(i), wlo + WOFF_GATE(i),
            win_b + (size_t)i * 2 * DMODEL, nullptr, nullptr, chi, clo);
        gemm_mma_kernel<1><<<dim3(2, 64), 256, GEMM_SMEM>>>(
            chi, clo, whi + WOFF_WOUT(i), wlo + WOFF_WOUT(i),
            wout_b + i * DMODEL, h, h, nullptr, nullptr);
    }

    // 6) final layer norm -> out
    ln_warp_kernel<<<MROWS / 8, 256>>>(h, fn_g, fn_b, out);

    // 7) comp_mask tail (all True -> 1.0f) if present in out buffer
    int main_elems = MROWS * DMODEL;
    int extra = out_size - main_elems;
    if (extra > 0)
        fill_ones_kernel<<<(extra + 255) / 256, 256>>>(out + main_elems, extra);
}